// round 14
// baseline (speedup 1.0000x reference)
#include <cuda_runtime.h>
#include <cuda_fp16.h>
#include <cuda_bf16.h>
#include <cstdint>

// ---------------------------------------------------------------------------
// Problem constants
// ---------------------------------------------------------------------------
#define BB    2
#define SS    1024
#define HID   4096
#define NH    64
#define NKV   8
#define HD    192
#define VD    128
#define ROT   64
#define WIN   128
#define SCALE 0.07216878364870323f   // 192^-0.5

#define NQ (NH * HD)     // 12288
#define NK (NKV * HD)    // 1536
#define NV (NKV * VD)    // 1024
#define NO (NH * VD)     // 8192
#define MM (BB * SS)     // 2048

// ---------------------------------------------------------------------------
// Scratch (device globals; no allocations allowed)
// ---------------------------------------------------------------------------
__device__ __half g_Qh [(size_t)MM * NQ];
__device__ __half g_Kh [(size_t)MM * NK];
__device__ __half g_Vh [(size_t)MM * NV];
__device__ __half g_Hh [(size_t)MM * HID];
__device__ __half g_Wqh[(size_t)HID * NQ];
__device__ __half g_Wkh[(size_t)HID * NK];
__device__ __half g_Wvh[(size_t)HID * NV];
__device__ __half g_Woh[(size_t)NO * HID];
__device__ __half g_AOh[(size_t)MM * NO];

// ---------------------------------------------------------------------------
// Helpers
// ---------------------------------------------------------------------------
__device__ __forceinline__ uint32_t smem_u32(const void* p) {
    return (uint32_t)__cvta_generic_to_shared(p);
}

#define CP_ASYNC16(dst, src) \
    asm volatile("cp.async.cg.shared.global [%0], [%1], 16;" \
                 :: "r"(dst), "l"(src))
#define CP_COMMIT() asm volatile("cp.async.commit_group;" ::: "memory")
#define CP_WAIT1()  asm volatile("cp.async.wait_group 1;"  ::: "memory")
#define CP_WAIT0()  asm volatile("cp.async.wait_group 0;"  ::: "memory")

#define LDSM_X4(r, addr)                                                       \
    asm volatile("ldmatrix.sync.aligned.m8n8.x4.shared.b16 {%0,%1,%2,%3}, [%4];" \
        : "=r"((r)[0]), "=r"((r)[1]), "=r"((r)[2]), "=r"((r)[3]) : "r"(addr))
#define LDSM_X4T(r, addr)                                                      \
    asm volatile("ldmatrix.sync.aligned.m8n8.x4.trans.shared.b16 {%0,%1,%2,%3}, [%4];" \
        : "=r"((r)[0]), "=r"((r)[1]), "=r"((r)[2]), "=r"((r)[3]) : "r"(addr))
#define MMA16816(c, a0, a1, a2, a3, b0, b1)                                    \
    asm volatile("mma.sync.aligned.m16n8k16.row.col.f32.f16.f16.f32 "          \
        "{%0,%1,%2,%3}, {%4,%5,%6,%7}, {%8,%9}, {%0,%1,%2,%3};"                \
        : "+f"((c)[0]), "+f"((c)[1]), "+f"((c)[2]), "+f"((c)[3])               \
        : "r"(a0), "r"(a1), "r"(a2), "r"(a3), "r"(b0), "r"(b1))

// ---------------------------------------------------------------------------
// fp16 mma.sync GEMM core: CTA 128x128, 4 warps (2x2 of 64x64), K-chunk 64,
// 3-stage cp.async pipeline, 2 CTAs/SM (128 threads/CTA).
// ---------------------------------------------------------------------------
#define APITCH_B  144
#define BPITCH_B  272
#define A_BYTES   (128 * APITCH_B)          // 18432
#define STAGE_B   (A_BYTES + 64 * BPITCH_B) // 35840
#define GEMM_SMEM (3 * STAGE_B)             // 107520

template <typename CT>
__device__ __forceinline__ void gemm_core(
    const __half* __restrict__ Ag, int lda,
    const __half* __restrict__ Bg, int ldb,
    CT* __restrict__ Cg, int ldc, int Kdim)
{
    extern __shared__ char smraw[];
    const uint32_t sb0 = smem_u32(smraw);
    const int tid = threadIdx.x, lane = tid & 31, warp = tid >> 5;
    const int wm = warp & 1, wn = warp >> 1;          // 2 x 2 warps of 64x64

    uint32_t aoff[4], boff[4];
#pragma unroll
    for (int mt = 0; mt < 4; mt++)
        aoff[mt] = (uint32_t)(wm * 64 + mt * 16 + (lane & 15)) * APITCH_B
                 + (uint32_t)(lane >> 4) * 16;
#pragma unroll
    for (int n2 = 0; n2 < 4; n2++)
        boff[n2] = A_BYTES + (uint32_t)(lane & 15) * BPITCH_B
                 + (uint32_t)(wn * 64 + n2 * 16) * 2
                 + (uint32_t)(lane >> 4) * 16;

    float acc[4][8][4];
#pragma unroll
    for (int mt = 0; mt < 4; mt++)
#pragma unroll
        for (int nt = 0; nt < 8; nt++)
#pragma unroll
            for (int r = 0; r < 4; r++) acc[mt][nt][r] = 0.f;

    const int KT = Kdim >> 6;
    // 128 threads: A 1024 chunks -> 8/thread; B 1024 chunks -> 8/thread
    const int am = tid >> 3, ac16 = tid & 7;      // A: rows (tid>>3)+16i
    const int bk = tid >> 4, bc16 = tid & 15;     // B: rows (tid>>4)+8i
#define ISSUE_COPY(ktc, s) do {                                                \
        const int _k0 = (ktc) * 64;                                            \
        const uint32_t _sa = sb0 + (s) * STAGE_B;                              \
        _Pragma("unroll")                                                      \
        for (int _i = 0; _i < 8; _i++)                                         \
            CP_ASYNC16(_sa + (am + _i * 16) * APITCH_B + ac16 * 16,            \
                       Ag + (size_t)(am + _i * 16) * lda + _k0 + ac16 * 8);    \
        _Pragma("unroll")                                                      \
        for (int _i = 0; _i < 8; _i++)                                         \
            CP_ASYNC16(_sa + A_BYTES + (bk + _i * 8) * BPITCH_B + bc16 * 16,   \
                       Bg + (size_t)(_k0 + bk + _i * 8) * ldb + bc16 * 8);     \
    } while (0)

#pragma unroll
    for (int p = 0; p < 2; p++) { ISSUE_COPY(p, p); CP_COMMIT(); }

    int slot = 0;
    for (int kt = 0; kt < KT; kt++) {
        CP_WAIT1();
        __syncthreads();
        const uint32_t sa = sb0 + slot * STAGE_B;

#pragma unroll
        for (int kk = 0; kk < 4; kk++) {
            uint32_t a[4][4], b[4][4];
#pragma unroll
            for (int mt = 0; mt < 4; mt++)
                LDSM_X4(a[mt], sa + aoff[mt] + kk * 32);
#pragma unroll
            for (int n2 = 0; n2 < 4; n2++)
                LDSM_X4T(b[n2], sa + boff[n2] + kk * (16 * BPITCH_B));
#pragma unroll
            for (int mt = 0; mt < 4; mt++)
#pragma unroll
                for (int nt = 0; nt < 8; nt++)
                    MMA16816(acc[mt][nt],
                             a[mt][0], a[mt][1], a[mt][2], a[mt][3],
                             b[nt >> 1][(nt & 1) * 2], b[nt >> 1][(nt & 1) * 2 + 1]);
        }

        const int ktc = kt + 2;
        if (ktc < KT) {
            int ws = slot + 2; if (ws >= 3) ws -= 3;
            ISSUE_COPY(ktc, ws);
        }
        CP_COMMIT();
        if (++slot == 3) slot = 0;
    }
#undef ISSUE_COPY

#pragma unroll
    for (int mt = 0; mt < 4; mt++) {
        const int r = wm * 64 + mt * 16 + (lane >> 2);
#pragma unroll
        for (int nt = 0; nt < 8; nt++) {
            const int cc = wn * 64 + nt * 8 + (lane & 3) * 2;
            if (sizeof(CT) == 2) {
                *(__half2*)&Cg[(size_t)r * ldc + cc] =
                    __floats2half2_rn(acc[mt][nt][0], acc[mt][nt][1]);
                *(__half2*)&Cg[(size_t)(r + 8) * ldc + cc] =
                    __floats2half2_rn(acc[mt][nt][2], acc[mt][nt][3]);
            } else {
                *(float2*)&Cg[(size_t)r * ldc + cc] =
                    make_float2(acc[mt][nt][0], acc[mt][nt][1]);
                *(float2*)&Cg[(size_t)(r + 8) * ldc + cc] =
                    make_float2(acc[mt][nt][2], acc[mt][nt][3]);
            }
        }
    }
}

__global__ __launch_bounds__(128, 2) void gemm_qkv(
    const __half* __restrict__ Hh,
    const __half* __restrict__ Wqh, const __half* __restrict__ Wkh,
    const __half* __restrict__ Wvh,
    __half* __restrict__ Q, __half* __restrict__ K, __half* __restrict__ V)
{
    const int col0 = blockIdx.x * 128, row0 = blockIdx.y * 128;
    const __half* Bg; __half* Cg; int ld;
    if (col0 < NQ)            { Bg = Wqh + col0;          Cg = Q + col0;          ld = NQ; }
    else if (col0 < NQ + NK)  { int c = col0 - NQ;  Bg = Wkh + c; Cg = K + c; ld = NK; }
    else                      { int c = col0 - NQ - NK; Bg = Wvh + c; Cg = V + c; ld = NV; }
    gemm_core<__half>(Hh + (size_t)row0 * HID, HID, Bg, ld,
                      Cg + (size_t)row0 * ld, ld, HID);
}

__global__ __launch_bounds__(128, 2) void gemm_gen(
    const __half* __restrict__ Ah, const __half* __restrict__ Bh,
    float* __restrict__ C, int lda, int ldb, int Kdim)
{
    const int col0 = blockIdx.x * 128, row0 = blockIdx.y * 128;
    gemm_core<float>(Ah + (size_t)row0 * lda, lda, Bh + col0, ldb,
                     C + (size_t)row0 * ldb + col0, ldb, Kdim);
}

// ---------------------------------------------------------------------------
// Merged fp32 -> fp16 conversion: one launch covers H, Wq, Wk, Wv, Wo.
// Each block converts 8192 elements (32/thread). Segment boundaries in blocks:
//   H 1024 | Wq 6144 | Wk 768 | Wv 512 | Wo 4096  (total 12544)
// ---------------------------------------------------------------------------
#define CB_H  1024
#define CB_WQ (CB_H + 6144)    // 7168
#define CB_WK (CB_WQ + 768)    // 7936
#define CB_WV (CB_WK + 512)    // 8448
#define CB_ALL (CB_WV + 4096)  // 12544

__global__ __launch_bounds__(256) void convert_all(
    const float* __restrict__ H,  const float* __restrict__ Wq,
    const float* __restrict__ Wk, const float* __restrict__ Wv,
    const float* __restrict__ Wo,
    __half* __restrict__ Hh,  __half* __restrict__ Wqh,
    __half* __restrict__ Wkh, __half* __restrict__ Wvh,
    __half* __restrict__ Woh)
{
    int blk = blockIdx.x;
    const float* in; __half* out;
    if      (blk < CB_H)  { in = H;  out = Hh; }
    else if (blk < CB_WQ) { in = Wq; out = Wqh; blk -= CB_H; }
    else if (blk < CB_WK) { in = Wk; out = Wkh; blk -= CB_WQ; }
    else if (blk < CB_WV) { in = Wv; out = Wvh; blk -= CB_WK; }
    else                  { in = Wo; out = Woh; blk -= CB_WV; }

    const size_t i = ((size_t)blk * 256 + threadIdx.x) * 32;
#pragma unroll
    for (int u = 0; u < 4; u++) {
        float4 a = *(const float4*)(in + i + u * 8);
        float4 b = *(const float4*)(in + i + u * 8 + 4);
        union { __half2 h[4]; uint4 v; } cv;
        cv.h[0] = __floats2half2_rn(a.x, a.y);
        cv.h[1] = __floats2half2_rn(a.z, a.w);
        cv.h[2] = __floats2half2_rn(b.x, b.y);
        cv.h[3] = __floats2half2_rn(b.z, b.w);
        *(uint4*)(out + i + u * 8) = cv.v;
    }
}

// ---------------------------------------------------------------------------
// Merged partial RoPE over Q and K (fp16 in place).
// Blocks [0, 16384) -> Q (64 heads); [16384, 18432) -> K (8 heads).
// ---------------------------------------------------------------------------
#define RB_Q (MM * NH * 32 / 256)      // 16384
#define RB_ALL (RB_Q + MM * NKV * 32 / 256)

__global__ __launch_bounds__(256) void rope_all(
    __half* __restrict__ Q, __half* __restrict__ K,
    const float* __restrict__ cosp, const float* __restrict__ sinp)
{
    int idx = blockIdx.x * 256 + threadIdx.x;
    __half* X; int nheads;
    if (blockIdx.x < RB_Q) { X = Q; nheads = NH; }
    else                   { X = K; nheads = NKV; idx -= RB_Q * 256; }

    int d  = idx & 31;
    int h  = (idx >> 5) % nheads;
    int bs = idx / (32 * nheads);

    __half* base = X + ((size_t)bs * nheads + h) * HD;
    float c = cosp[bs * ROT + d];
    float s = sinp[bs * ROT + d];
    float x1 = __half2float(base[d]), x2 = __half2float(base[d + 32]);
    base[d]      = __float2half_rn(x1 * c - x2 * s);
    base[d + 32] = __float2half_rn(x2 * c + x1 * s);
}

// ---------------------------------------------------------------------------
// Tensor-core sliding-window attention with sink (V load overlapped).
// ---------------------------------------------------------------------------
#define QPB 400
#define VPB 272
#define SQ_OFF 0
#define SK_OFF (128 * QPB)            // 51200
#define SV_OFF (SK_OFF + 160 * QPB)   // 115200
#define ATT_SMEM (SV_OFF + 160 * VPB) // 158720

__global__ __launch_bounds__(256, 1) void attn_kernel(
    const __half* __restrict__ Q, const __half* __restrict__ K,
    const __half* __restrict__ V, const float* __restrict__ sinks,
    __half* __restrict__ O)
{
    extern __shared__ char smatt[];
    const uint32_t sb = smem_u32(smatt);
    const int qt = blockIdx.x, kh = blockIdx.y, b = blockIdx.z;
    const int qs0 = qt * 16;
    const int jn0 = max(0, qs0 - (WIN - 1));
    const int tid = threadIdx.x, lane = tid & 31, w = tid >> 5;

    // group 0: Q + K
#pragma unroll
    for (int i = 0; i < 12; i++) {
        int c = tid + 256 * i;
        int r = c / 24, cc = c - r * 24;
        const __half* src = Q + (((size_t)b * SS + qs0 + (r & 15)) * NH
                                 + kh * 8 + (r >> 4)) * HD + cc * 8;
        CP_ASYNC16(sb + SQ_OFF + r * QPB + cc * 16, src);
    }
#pragma unroll
    for (int i = 0; i < 15; i++) {
        int c = tid + 256 * i;
        int j = c / 24, cc = c - j * 24;
        int sj = min(jn0 + j, SS - 1);
        const __half* src = K + (((size_t)b * SS + sj) * NKV + kh) * HD + cc * 8;
        CP_ASYNC16(sb + SK_OFF + j * QPB + cc * 16, src);
    }
    CP_COMMIT();
    // group 1: V (overlaps with score MMA)
#pragma unroll
    for (int i = 0; i < 10; i++) {
        int c = tid + 256 * i;
        int j = c >> 4, cc = c & 15;
        int sj = min(jn0 + j, SS - 1);
        const __half* src = V + (((size_t)b * SS + sj) * NKV + kh) * VD + cc * 8;
        CP_ASYNC16(sb + SV_OFF + j * VPB + cc * 16, src);
    }
    CP_COMMIT();

    CP_WAIT1();            // Q + K ready; V still in flight
    __syncthreads();

    // ---- score MMA ----
    float sacc[20][4];
#pragma unroll
    for (int nt = 0; nt < 20; nt++)
#pragma unroll
        for (int r = 0; r < 4; r++) sacc[nt][r] = 0.f;

    const uint32_t qbase = sb + SQ_OFF + (w * 16 + (lane & 15)) * QPB
                         + (lane >> 4) * 16;
    const uint32_t kbase = sb + SK_OFF + ((lane & 7) + ((lane >> 1) & 8)) * QPB
                         + (lane & 8) * 2;
#pragma unroll
    for (int ks = 0; ks < 12; ks++) {
        uint32_t a[4];
        LDSM_X4(a, qbase + ks * 32);
#pragma unroll
        for (int t = 0; t < 10; t++) {
            uint32_t bf[4];
            LDSM_X4(bf, kbase + t * (16 * QPB) + ks * 32);
            MMA16816(sacc[2 * t],     a[0], a[1], a[2], a[3], bf[0], bf[1]);
            MMA16816(sacc[2 * t + 1], a[0], a[1], a[2], a[3], bf[2], bf[3]);
        }
    }

    // ---- register softmax ----
    const int s0r = qs0 + (lane >> 2), s1r = s0r + 8;
    const float snk = sinks[kh * 8 + w];
    float m0 = snk, m1 = snk;
#pragma unroll
    for (int nt = 0; nt < 20; nt++) {
#pragma unroll
        for (int e = 0; e < 2; e++) {
            int jg = jn0 + nt * 8 + (lane & 3) * 2 + e;
            bool v0 = (jg <= s0r) && (s0r - jg < WIN);
            bool v1 = (jg <= s1r) && (s1r - jg < WIN);
            sacc[nt][e]     = v0 ? sacc[nt][e] * SCALE     : -1e30f;
            sacc[nt][e + 2] = v1 ? sacc[nt][e + 2] * SCALE : -1e30f;
            m0 = fmaxf(m0, sacc[nt][e]);
            m1 = fmaxf(m1, sacc[nt][e + 2]);
        }
    }
    m0 = fmaxf(m0, __shfl_xor_sync(0xffffffffu, m0, 1));
    m0 = fmaxf(m0, __shfl_xor_sync(0xffffffffu, m0, 2));
    m1 = fmaxf(m1, __shfl_xor_sync(0xffffffffu, m1, 1));
    m1 = fmaxf(m1, __shfl_xor_sync(0xffffffffu, m1, 2));

    float sum0 = 0.f, sum1 = 0.f;
    uint32_t p16[20][2];
#pragma unroll
    for (int nt = 0; nt < 20; nt++) {
        float p0 = expf(sacc[nt][0] - m0), p1 = expf(sacc[nt][1] - m0);
        float p2 = expf(sacc[nt][2] - m1), p3 = expf(sacc[nt][3] - m1);
        sum0 += p0 + p1; sum1 += p2 + p3;
        union { __half2 h; uint32_t u; } c01, c23;
        c01.h = __floats2half2_rn(p0, p1);
        c23.h = __floats2half2_rn(p2, p3);
        p16[nt][0] = c01.u; p16[nt][1] = c23.u;
    }
    sum0 += __shfl_xor_sync(0xffffffffu, sum0, 1);
    sum0 += __shfl_xor_sync(0xffffffffu, sum0, 2);
    sum1 += __shfl_xor_sync(0xffffffffu, sum1, 1);
    sum1 += __shfl_xor_sync(0xffffffffu, sum1, 2);
    sum0 += expf(snk - m0);
    sum1 += expf(snk - m1);
    const float inv0 = 1.f / sum0, inv1 = 1.f / sum1;

    CP_WAIT0();            // V ready
    __syncthreads();

    // ---- PV MMA ----
    float oacc[16][4];
#pragma unroll
    for (int nt = 0; nt < 16; nt++)
#pragma unroll
        for (int r = 0; r < 4; r++) oacc[nt][r] = 0.f;

    const uint32_t vbase = sb + SV_OFF + (lane & 15) * VPB + (lane >> 4) * 16;
#pragma unroll
    for (int t = 0; t < 10; t++) {
#pragma unroll
        for (int n = 0; n < 8; n++) {
            uint32_t bf[4];
            LDSM_X4T(bf, vbase + t * (16 * VPB) + n * 32);
            MMA16816(oacc[2 * n],     p16[2 * t][0], p16[2 * t][1],
                     p16[2 * t + 1][0], p16[2 * t + 1][1], bf[0], bf[1]);
            MMA16816(oacc[2 * n + 1], p16[2 * t][0], p16[2 * t][1],
                     p16[2 * t + 1][0], p16[2 * t + 1][1], bf[2], bf[3]);
        }
    }

    // ---- epilogue ----
    const int h = kh * 8 + w;
#pragma unroll
    for (int nt = 0; nt < 16; nt++) {
        int d = nt * 8 + (lane & 3) * 2;
        __half* o0 = O + (((size_t)b * SS + s0r) * NH + h) * VD + d;
        __half* o1 = O + (((size_t)b * SS + s1r) * NH + h) * VD + d;
        *(__half2*)o0 = __floats2half2_rn(oacc[nt][0] * inv0, oacc[nt][1] * inv0);
        *(__half2*)o1 = __floats2half2_rn(oacc[nt][2] * inv1, oacc[nt][3] * inv1);
    }
}

// ---------------------------------------------------------------------------
// Launcher
// ---------------------------------------------------------------------------
extern "C" void kernel_launch(void* const* d_in, const int* in_sizes, int n_in,
                              void* d_out, int out_size)
{
    const float* H     = (const float*)d_in[0];
    const float* cosp  = (const float*)d_in[1];
    const float* sinp  = (const float*)d_in[2];
    const float* Wq    = (const float*)d_in[3];
    const float* Wk    = (const float*)d_in[4];
    const float* Wv    = (const float*)d_in[5];
    const float* Wo    = (const float*)d_in[6];
    const float* sinks = (const float*)d_in[7];
    float* out = (float*)d_out;

    __half *Qh, *Kh, *Vh, *Hh, *Wqh, *Wkh, *Wvh, *Woh, *AOh;
    cudaGetSymbolAddress((void**)&Qh,  g_Qh);
    cudaGetSymbolAddress((void**)&Kh,  g_Kh);
    cudaGetSymbolAddress((void**)&Vh,  g_Vh);
    cudaGetSymbolAddress((void**)&Hh,  g_Hh);
    cudaGetSymbolAddress((void**)&Wqh, g_Wqh);
    cudaGetSymbolAddress((void**)&Wkh, g_Wkh);
    cudaGetSymbolAddress((void**)&Wvh, g_Wvh);
    cudaGetSymbolAddress((void**)&Woh, g_Woh);
    cudaGetSymbolAddress((void**)&AOh, g_AOh);

    static bool attr_set = false;
    if (!attr_set) {
        cudaFuncSetAttribute(gemm_qkv,
                             cudaFuncAttributeMaxDynamicSharedMemorySize, GEMM_SMEM);
        cudaFuncSetAttribute(gemm_gen,
                             cudaFuncAttributeMaxDynamicSharedMemorySize, GEMM_SMEM);
        cudaFuncSetAttribute(attn_kernel,
                             cudaFuncAttributeMaxDynamicSharedMemorySize, ATT_SMEM);
        attr_set = true;
    }

    // merged fp32 -> fp16 conversions
    convert_all<<<CB_ALL, 256>>>(H, Wq, Wk, Wv, Wo, Hh, Wqh, Wkh, Wvh, Woh);

    // fused QKV projection (fp16 out, 4-warp CTAs)
    gemm_qkv<<<dim3((NQ + NK + NV) / 128, MM / 128), 128, GEMM_SMEM>>>(
        Hh, Wqh, Wkh, Wvh, Qh, Kh, Vh);

    // merged partial RoPE (Q + K)
    rope_all<<<RB_ALL, 256>>>(Qh, Kh, cosp, sinp);

    // tensor-core attention -> fp16 AO
    attn_kernel<<<dim3(SS / 16, NKV, BB), 256, ATT_SMEM>>>(Qh, Kh, Vh, sinks, AOh);

    // output projection (fp32 out)
    gemm_gen<<<dim3(HID / 128, MM / 128), 128, GEMM_SMEM>>>(
        AOh, Woh, out, NO, HID, NO);
}

// round 17
// speedup vs baseline: 1.0267x; 1.0267x over previous
#include <cuda_runtime.h>
#include <cuda_fp16.h>
#include <cuda_bf16.h>
#include <cstdint>

// ---------------------------------------------------------------------------
// Problem constants
// ---------------------------------------------------------------------------
#define BB    2
#define SS    1024
#define HID   4096
#define NH    64
#define NKV   8
#define HD    192
#define VD    128
#define ROT   64
#define WIN   128
#define SCALE 0.07216878364870323f   // 192^-0.5

#define NQ (NH * HD)     // 12288
#define NK (NKV * HD)    // 1536
#define NV (NKV * VD)    // 1024
#define NO (NH * VD)     // 8192
#define MM (BB * SS)     // 2048

// ---------------------------------------------------------------------------
// Scratch (device globals; no allocations allowed)
// ---------------------------------------------------------------------------
__device__ __half g_Qh [(size_t)MM * NQ];
__device__ __half g_Kh [(size_t)MM * NK];
__device__ __half g_Vh [(size_t)MM * NV];
__device__ __half g_Hh [(size_t)MM * HID];
__device__ __half g_Wqh[(size_t)HID * NQ];
__device__ __half g_Wkh[(size_t)HID * NK];
__device__ __half g_Wvh[(size_t)HID * NV];
__device__ __half g_Woh[(size_t)NO * HID];
__device__ __half g_AOh[(size_t)MM * NO];

// ---------------------------------------------------------------------------
// Helpers
// ---------------------------------------------------------------------------
__device__ __forceinline__ uint32_t smem_u32(const void* p) {
    return (uint32_t)__cvta_generic_to_shared(p);
}

#define CP_ASYNC16(dst, src) \
    asm volatile("cp.async.cg.shared.global [%0], [%1], 16;" \
                 :: "r"(dst), "l"(src))
#define CP_COMMIT() asm volatile("cp.async.commit_group;" ::: "memory")
#define CP_WAIT1()  asm volatile("cp.async.wait_group 1;"  ::: "memory")
#define CP_WAIT0()  asm volatile("cp.async.wait_group 0;"  ::: "memory")

#define LDSM_X4(r, addr)                                                       \
    asm volatile("ldmatrix.sync.aligned.m8n8.x4.shared.b16 {%0,%1,%2,%3}, [%4];" \
        : "=r"((r)[0]), "=r"((r)[1]), "=r"((r)[2]), "=r"((r)[3]) : "r"(addr))
#define LDSM_X4T(r, addr)                                                      \
    asm volatile("ldmatrix.sync.aligned.m8n8.x4.trans.shared.b16 {%0,%1,%2,%3}, [%4];" \
        : "=r"((r)[0]), "=r"((r)[1]), "=r"((r)[2]), "=r"((r)[3]) : "r"(addr))
#define MMA16816(c, a0, a1, a2, a3, b0, b1)                                    \
    asm volatile("mma.sync.aligned.m16n8k16.row.col.f32.f16.f16.f32 "          \
        "{%0,%1,%2,%3}, {%4,%5,%6,%7}, {%8,%9}, {%0,%1,%2,%3};"                \
        : "+f"((c)[0]), "+f"((c)[1]), "+f"((c)[2]), "+f"((c)[3])               \
        : "r"(a0), "r"(a1), "r"(a2), "r"(a3), "r"(b0), "r"(b1))

// ---------------------------------------------------------------------------
// fp16 mma.sync GEMM core (round-13 winner): CTA 128x128, 8 warps (2x4,
// 64x32 each), K-chunk 64, 3-stage cp.async pipeline, 2 CTAs/SM.
// ---------------------------------------------------------------------------
#define APITCH_B  144
#define BPITCH_B  272
#define A_BYTES   (128 * APITCH_B)          // 18432
#define STAGE_B   (A_BYTES + 64 * BPITCH_B) // 35840
#define GEMM_SMEM (3 * STAGE_B)             // 107520

template <typename CT>
__device__ __forceinline__ void gemm_core(
    const __half* __restrict__ Ag, int lda,
    const __half* __restrict__ Bg, int ldb,
    CT* __restrict__ Cg, int ldc, int Kdim)
{
    extern __shared__ char smraw[];
    const uint32_t sb0 = smem_u32(smraw);
    const int tid = threadIdx.x, lane = tid & 31, warp = tid >> 5;
    const int wm = warp & 1, wn = warp >> 1;

    uint32_t aoff[4], boff[2];
#pragma unroll
    for (int mt = 0; mt < 4; mt++)
        aoff[mt] = (uint32_t)(wm * 64 + mt * 16 + (lane & 15)) * APITCH_B
                 + (uint32_t)(lane >> 4) * 16;
#pragma unroll
    for (int n2 = 0; n2 < 2; n2++)
        boff[n2] = A_BYTES + (uint32_t)(lane & 15) * BPITCH_B
                 + (uint32_t)(wn * 32 + n2 * 16) * 2
                 + (uint32_t)(lane >> 4) * 16;

    float acc[4][4][4];
#pragma unroll
    for (int mt = 0; mt < 4; mt++)
#pragma unroll
        for (int nt = 0; nt < 4; nt++)
#pragma unroll
            for (int r = 0; r < 4; r++) acc[mt][nt][r] = 0.f;

    const int KT = Kdim >> 6;
    const int am = tid >> 3, ac16 = tid & 7;
    const int bk = tid >> 4, bc16 = tid & 15;
#define ISSUE_COPY(ktc, s) do {                                                \
        const int _k0 = (ktc) * 64;                                            \
        const uint32_t _sa = sb0 + (s) * STAGE_B;                              \
        _Pragma("unroll")                                                      \
        for (int _i = 0; _i < 4; _i++)                                         \
            CP_ASYNC16(_sa + (am + _i * 32) * APITCH_B + ac16 * 16,            \
                       Ag + (size_t)(am + _i * 32) * lda + _k0 + ac16 * 8);    \
        _Pragma("unroll")                                                      \
        for (int _i = 0; _i < 4; _i++)                                         \
            CP_ASYNC16(_sa + A_BYTES + (bk + _i * 16) * BPITCH_B + bc16 * 16,  \
                       Bg + (size_t)(_k0 + bk + _i * 16) * ldb + bc16 * 8);    \
    } while (0)

#pragma unroll
    for (int p = 0; p < 2; p++) { ISSUE_COPY(p, p); CP_COMMIT(); }

    int slot = 0;
    for (int kt = 0; kt < KT; kt++) {
        CP_WAIT1();
        __syncthreads();
        const uint32_t sa = sb0 + slot * STAGE_B;

#pragma unroll
        for (int kk = 0; kk < 4; kk++) {
            uint32_t a[4][4], b[2][4];
#pragma unroll
            for (int mt = 0; mt < 4; mt++)
                LDSM_X4(a[mt], sa + aoff[mt] + kk * 32);
#pragma unroll
            for (int n2 = 0; n2 < 2; n2++)
                LDSM_X4T(b[n2], sa + boff[n2] + kk * (16 * BPITCH_B));
#pragma unroll
            for (int mt = 0; mt < 4; mt++)
#pragma unroll
                for (int nt = 0; nt < 4; nt++)
                    MMA16816(acc[mt][nt],
                             a[mt][0], a[mt][1], a[mt][2], a[mt][3],
                             b[nt >> 1][(nt & 1) * 2], b[nt >> 1][(nt & 1) * 2 + 1]);
        }

        const int ktc = kt + 2;
        if (ktc < KT) {
            int ws = slot + 2; if (ws >= 3) ws -= 3;
            ISSUE_COPY(ktc, ws);
        }
        CP_COMMIT();
        if (++slot == 3) slot = 0;
    }
#undef ISSUE_COPY

#pragma unroll
    for (int mt = 0; mt < 4; mt++) {
        const int r = wm * 64 + mt * 16 + (lane >> 2);
#pragma unroll
        for (int nt = 0; nt < 4; nt++) {
            const int cc = wn * 32 + nt * 8 + (lane & 3) * 2;
            if (sizeof(CT) == 2) {
                *(__half2*)&Cg[(size_t)r * ldc + cc] =
                    __floats2half2_rn(acc[mt][nt][0], acc[mt][nt][1]);
                *(__half2*)&Cg[(size_t)(r + 8) * ldc + cc] =
                    __floats2half2_rn(acc[mt][nt][2], acc[mt][nt][3]);
            } else {
                *(float2*)&Cg[(size_t)r * ldc + cc] =
                    make_float2(acc[mt][nt][0], acc[mt][nt][1]);
                *(float2*)&Cg[(size_t)(r + 8) * ldc + cc] =
                    make_float2(acc[mt][nt][2], acc[mt][nt][3]);
            }
        }
    }
}

__global__ __launch_bounds__(256, 2) void gemm_qkv(
    const __half* __restrict__ Hh,
    const __half* __restrict__ Wqh, const __half* __restrict__ Wkh,
    const __half* __restrict__ Wvh,
    __half* __restrict__ Q, __half* __restrict__ K, __half* __restrict__ V)
{
    const int col0 = blockIdx.x * 128, row0 = blockIdx.y * 128;
    const __half* Bg; __half* Cg; int ld;
    if (col0 < NQ)            { Bg = Wqh + col0;          Cg = Q + col0;          ld = NQ; }
    else if (col0 < NQ + NK)  { int c = col0 - NQ;  Bg = Wkh + c; Cg = K + c; ld = NK; }
    else                      { int c = col0 - NQ - NK; Bg = Wvh + c; Cg = V + c; ld = NV; }
    gemm_core<__half>(Hh + (size_t)row0 * HID, HID, Bg, ld,
                      Cg + (size_t)row0 * ld, ld, HID);
}

__global__ __launch_bounds__(256, 2) void gemm_gen(
    const __half* __restrict__ Ah, const __half* __restrict__ Bh,
    float* __restrict__ C, int lda, int ldb, int Kdim)
{
    const int col0 = blockIdx.x * 128, row0 = blockIdx.y * 128;
    gemm_core<float>(Ah + (size_t)row0 * lda, lda, Bh + col0, ldb,
                     C + (size_t)row0 * ldb + col0, ldb, Kdim);
}

// ---------------------------------------------------------------------------
// fp32 -> fp16 conversions. convert_pre covers H|Wq|Wk|Wv (critical path);
// convert_wo covers Wo (runs on forked stream, hidden under QKV GEMM).
// 8192 elems per block (32/thread).
// ---------------------------------------------------------------------------
__device__ __forceinline__ void conv_block(
    const float* __restrict__ in, __half* __restrict__ out, int blk)
{
    const size_t i = ((size_t)blk * 256 + threadIdx.x) * 32;
#pragma unroll
    for (int u = 0; u < 4; u++) {
        float4 a = *(const float4*)(in + i + u * 8);
        float4 b = *(const float4*)(in + i + u * 8 + 4);
        union { __half2 h[4]; uint4 v; } cv;
        cv.h[0] = __floats2half2_rn(a.x, a.y);
        cv.h[1] = __floats2half2_rn(a.z, a.w);
        cv.h[2] = __floats2half2_rn(b.x, b.y);
        cv.h[3] = __floats2half2_rn(b.z, b.w);
        *(uint4*)(out + i + u * 8) = cv.v;
    }
}

#define CB_H  1024
#define CB_WQ (CB_H + 6144)    // 7168
#define CB_WK (CB_WQ + 768)    // 7936
#define CB_PRE (CB_WK + 512)   // 8448
#define CB_WO 4096

__global__ __launch_bounds__(256) void convert_pre(
    const float* __restrict__ H,  const float* __restrict__ Wq,
    const float* __restrict__ Wk, const float* __restrict__ Wv,
    __half* __restrict__ Hh,  __half* __restrict__ Wqh,
    __half* __restrict__ Wkh, __half* __restrict__ Wvh)
{
    int blk = blockIdx.x;
    if      (blk < CB_H)  conv_block(H,  Hh,  blk);
    else if (blk < CB_WQ) conv_block(Wq, Wqh, blk - CB_H);
    else if (blk < CB_WK) conv_block(Wk, Wkh, blk - CB_WQ);
    else                  conv_block(Wv, Wvh, blk - CB_WK);
}

__global__ __launch_bounds__(256) void convert_wo(
    const float* __restrict__ Wo, __half* __restrict__ Woh)
{
    conv_block(Wo, Woh, blockIdx.x);
}

// ---------------------------------------------------------------------------
// Merged partial RoPE over Q and K (fp16 in place).
// ---------------------------------------------------------------------------
#define RB_Q (MM * NH * 32 / 256)      // 16384
#define RB_ALL (RB_Q + MM * NKV * 32 / 256)

__global__ __launch_bounds__(256) void rope_all(
    __half* __restrict__ Q, __half* __restrict__ K,
    const float* __restrict__ cosp, const float* __restrict__ sinp)
{
    int idx = blockIdx.x * 256 + threadIdx.x;
    __half* X; int nheads;
    if (blockIdx.x < RB_Q) { X = Q; nheads = NH; }
    else                   { X = K; nheads = NKV; idx -= RB_Q * 256; }

    int d  = idx & 31;
    int h  = (idx >> 5) % nheads;
    int bs = idx / (32 * nheads);

    __half* base = X + ((size_t)bs * nheads + h) * HD;
    float c = cosp[bs * ROT + d];
    float s = sinp[bs * ROT + d];
    float x1 = __half2float(base[d]), x2 = __half2float(base[d + 32]);
    base[d]      = __float2half_rn(x1 * c - x2 * s);
    base[d + 32] = __float2half_rn(x2 * c + x1 * s);
}

// ---------------------------------------------------------------------------
// Tensor-core sliding-window attention with sink (V load overlapped).
// ---------------------------------------------------------------------------
#define QPB 400
#define VPB 272
#define SQ_OFF 0
#define SK_OFF (128 * QPB)            // 51200
#define SV_OFF (SK_OFF + 160 * QPB)   // 115200
#define ATT_SMEM (SV_OFF + 160 * VPB) // 158720

__global__ __launch_bounds__(256, 1) void attn_kernel(
    const __half* __restrict__ Q, const __half* __restrict__ K,
    const __half* __restrict__ V, const float* __restrict__ sinks,
    __half* __restrict__ O)
{
    extern __shared__ char smatt[];
    const uint32_t sb = smem_u32(smatt);
    const int qt = blockIdx.x, kh = blockIdx.y, b = blockIdx.z;
    const int qs0 = qt * 16;
    const int jn0 = max(0, qs0 - (WIN - 1));
    const int tid = threadIdx.x, lane = tid & 31, w = tid >> 5;

    // group 0: Q + K
#pragma unroll
    for (int i = 0; i < 12; i++) {
        int c = tid + 256 * i;
        int r = c / 24, cc = c - r * 24;
        const __half* src = Q + (((size_t)b * SS + qs0 + (r & 15)) * NH
                                 + kh * 8 + (r >> 4)) * HD + cc * 8;
        CP_ASYNC16(sb + SQ_OFF + r * QPB + cc * 16, src);
    }
#pragma unroll
    for (int i = 0; i < 15; i++) {
        int c = tid + 256 * i;
        int j = c / 24, cc = c - j * 24;
        int sj = min(jn0 + j, SS - 1);
        const __half* src = K + (((size_t)b * SS + sj) * NKV + kh) * HD + cc * 8;
        CP_ASYNC16(sb + SK_OFF + j * QPB + cc * 16, src);
    }
    CP_COMMIT();
    // group 1: V (overlaps with score MMA)
#pragma unroll
    for (int i = 0; i < 10; i++) {
        int c = tid + 256 * i;
        int j = c >> 4, cc = c & 15;
        int sj = min(jn0 + j, SS - 1);
        const __half* src = V + (((size_t)b * SS + sj) * NKV + kh) * VD + cc * 8;
        CP_ASYNC16(sb + SV_OFF + j * VPB + cc * 16, src);
    }
    CP_COMMIT();

    CP_WAIT1();
    __syncthreads();

    // ---- score MMA ----
    float sacc[20][4];
#pragma unroll
    for (int nt = 0; nt < 20; nt++)
#pragma unroll
        for (int r = 0; r < 4; r++) sacc[nt][r] = 0.f;

    const uint32_t qbase = sb + SQ_OFF + (w * 16 + (lane & 15)) * QPB
                         + (lane >> 4) * 16;
    const uint32_t kbase = sb + SK_OFF + ((lane & 7) + ((lane >> 1) & 8)) * QPB
                         + (lane & 8) * 2;
#pragma unroll
    for (int ks = 0; ks < 12; ks++) {
        uint32_t a[4];
        LDSM_X4(a, qbase + ks * 32);
#pragma unroll
        for (int t = 0; t < 10; t++) {
            uint32_t bf[4];
            LDSM_X4(bf, kbase + t * (16 * QPB) + ks * 32);
            MMA16816(sacc[2 * t],     a[0], a[1], a[2], a[3], bf[0], bf[1]);
            MMA16816(sacc[2 * t + 1], a[0], a[1], a[2], a[3], bf[2], bf[3]);
        }
    }

    // ---- register softmax ----
    const int s0r = qs0 + (lane >> 2), s1r = s0r + 8;
    const float snk = sinks[kh * 8 + w];
    float m0 = snk, m1 = snk;
#pragma unroll
    for (int nt = 0; nt < 20; nt++) {
#pragma unroll
        for (int e = 0; e < 2; e++) {
            int jg = jn0 + nt * 8 + (lane & 3) * 2 + e;
            bool v0 = (jg <= s0r) && (s0r - jg < WIN);
            bool v1 = (jg <= s1r) && (s1r - jg < WIN);
            sacc[nt][e]     = v0 ? sacc[nt][e] * SCALE     : -1e30f;
            sacc[nt][e + 2] = v1 ? sacc[nt][e + 2] * SCALE : -1e30f;
            m0 = fmaxf(m0, sacc[nt][e]);
            m1 = fmaxf(m1, sacc[nt][e + 2]);
        }
    }
    m0 = fmaxf(m0, __shfl_xor_sync(0xffffffffu, m0, 1));
    m0 = fmaxf(m0, __shfl_xor_sync(0xffffffffu, m0, 2));
    m1 = fmaxf(m1, __shfl_xor_sync(0xffffffffu, m1, 1));
    m1 = fmaxf(m1, __shfl_xor_sync(0xffffffffu, m1, 2));

    float sum0 = 0.f, sum1 = 0.f;
    uint32_t p16[20][2];
#pragma unroll
    for (int nt = 0; nt < 20; nt++) {
        float p0 = expf(sacc[nt][0] - m0), p1 = expf(sacc[nt][1] - m0);
        float p2 = expf(sacc[nt][2] - m1), p3 = expf(sacc[nt][3] - m1);
        sum0 += p0 + p1; sum1 += p2 + p3;
        union { __half2 h; uint32_t u; } c01, c23;
        c01.h = __floats2half2_rn(p0, p1);
        c23.h = __floats2half2_rn(p2, p3);
        p16[nt][0] = c01.u; p16[nt][1] = c23.u;
    }
    sum0 += __shfl_xor_sync(0xffffffffu, sum0, 1);
    sum0 += __shfl_xor_sync(0xffffffffu, sum0, 2);
    sum1 += __shfl_xor_sync(0xffffffffu, sum1, 1);
    sum1 += __shfl_xor_sync(0xffffffffu, sum1, 2);
    sum0 += expf(snk - m0);
    sum1 += expf(snk - m1);
    const float inv0 = 1.f / sum0, inv1 = 1.f / sum1;

    CP_WAIT0();
    __syncthreads();

    // ---- PV MMA ----
    float oacc[16][4];
#pragma unroll
    for (int nt = 0; nt < 16; nt++)
#pragma unroll
        for (int r = 0; r < 4; r++) oacc[nt][r] = 0.f;

    const uint32_t vbase = sb + SV_OFF + (lane & 15) * VPB + (lane >> 4) * 16;
#pragma unroll
    for (int t = 0; t < 10; t++) {
#pragma unroll
        for (int n = 0; n < 8; n++) {
            uint32_t bf[4];
            LDSM_X4T(bf, vbase + t * (16 * VPB) + n * 32);
            MMA16816(oacc[2 * n],     p16[2 * t][0], p16[2 * t][1],
                     p16[2 * t + 1][0], p16[2 * t + 1][1], bf[0], bf[1]);
            MMA16816(oacc[2 * n + 1], p16[2 * t][0], p16[2 * t][1],
                     p16[2 * t + 1][0], p16[2 * t + 1][1], bf[2], bf[3]);
        }
    }

    // ---- epilogue ----
    const int h = kh * 8 + w;
#pragma unroll
    for (int nt = 0; nt < 16; nt++) {
        int d = nt * 8 + (lane & 3) * 2;
        __half* o0 = O + (((size_t)b * SS + s0r) * NH + h) * VD + d;
        __half* o1 = O + (((size_t)b * SS + s1r) * NH + h) * VD + d;
        *(__half2*)o0 = __floats2half2_rn(oacc[nt][0] * inv0, oacc[nt][1] * inv0);
        *(__half2*)o1 = __floats2half2_rn(oacc[nt][2] * inv1, oacc[nt][3] * inv1);
    }
}

// ---------------------------------------------------------------------------
// Launcher (graph-capturable fork/join: Wo conversion overlaps QKV GEMM)
// ---------------------------------------------------------------------------
extern "C" void kernel_launch(void* const* d_in, const int* in_sizes, int n_in,
                              void* d_out, int out_size)
{
    const float* H     = (const float*)d_in[0];
    const float* cosp  = (const float*)d_in[1];
    const float* sinp  = (const float*)d_in[2];
    const float* Wq    = (const float*)d_in[3];
    const float* Wk    = (const float*)d_in[4];
    const float* Wv    = (const float*)d_in[5];
    const float* Wo    = (const float*)d_in[6];
    const float* sinks = (const float*)d_in[7];
    float* out = (float*)d_out;

    __half *Qh, *Kh, *Vh, *Hh, *Wqh, *Wkh, *Wvh, *Woh, *AOh;
    cudaGetSymbolAddress((void**)&Qh,  g_Qh);
    cudaGetSymbolAddress((void**)&Kh,  g_Kh);
    cudaGetSymbolAddress((void**)&Vh,  g_Vh);
    cudaGetSymbolAddress((void**)&Hh,  g_Hh);
    cudaGetSymbolAddress((void**)&Wqh, g_Wqh);
    cudaGetSymbolAddress((void**)&Wkh, g_Wkh);
    cudaGetSymbolAddress((void**)&Wvh, g_Wvh);
    cudaGetSymbolAddress((void**)&Woh, g_Woh);
    cudaGetSymbolAddress((void**)&AOh, g_AOh);

    static bool init_done = false;
    static cudaStream_t s2;
    static cudaEvent_t evFork, evJoin;
    if (!init_done) {
        cudaFuncSetAttribute(gemm_qkv,
                             cudaFuncAttributeMaxDynamicSharedMemorySize, GEMM_SMEM);
        cudaFuncSetAttribute(gemm_gen,
                             cudaFuncAttributeMaxDynamicSharedMemorySize, GEMM_SMEM);
        cudaFuncSetAttribute(attn_kernel,
                             cudaFuncAttributeMaxDynamicSharedMemorySize, ATT_SMEM);
        cudaStreamCreateWithFlags(&s2, cudaStreamNonBlocking);
        cudaEventCreateWithFlags(&evFork, cudaEventDisableTiming);
        cudaEventCreateWithFlags(&evJoin, cudaEventDisableTiming);
        init_done = true;
    }

    // critical-path conversions (H, Wq, Wk, Wv)
    convert_pre<<<CB_PRE, 256>>>(H, Wq, Wk, Wv, Hh, Wqh, Wkh, Wvh);

    // fork: Wo conversion overlaps the QKV GEMM + rope + attention
    cudaEventRecord(evFork, 0);
    cudaStreamWaitEvent(s2, evFork, 0);
    convert_wo<<<CB_WO, 256, 0, s2>>>(Wo, Woh);
    cudaEventRecord(evJoin, s2);

    // fused QKV projection (fp16 out)
    gemm_qkv<<<dim3((NQ + NK + NV) / 128, MM / 128), 256, GEMM_SMEM>>>(
        Hh, Wqh, Wkh, Wvh, Qh, Kh, Vh);

    // merged partial RoPE (Q + K)
    rope_all<<<RB_ALL, 256>>>(Qh, Kh, cosp, sinp);

    // tensor-core attention -> fp16 AO
    attn_kernel<<<dim3(SS / 16, NKV, BB), 256, ATT_SMEM>>>(Qh, Kh, Vh, sinks, AOh);

    // join: Woh must be ready before the output projection
    cudaStreamWaitEvent(0, evJoin, 0);
    gemm_gen<<<dim3(HID / 128, MM / 128), 256, GEMM_SMEM>>>(
        AOh, Woh, out, NO, HID, NO);
}